// round 2
// baseline (speedup 1.0000x reference)
#include <cuda_runtime.h>
#include <cuda_fp16.h>
#include <math.h>

#define B_   4096
#define N_   32
#define D_   256
#define NT   4
#define NH   8
#define TOK  131072        // B_*N_
#define WSZ  65536         // 256*256

// ---------------- scratch (static device allocations) ----------------
__device__ __half g_W16[(size_t)3 * NT * WSZ];          // [mat][e][k][n] fp16, 1.5MB
__device__ __half g_QKV[(size_t)3 * TOK * D_];          // [mat][token][c] fp16, 201MB
__device__ float  g_out[(size_t)B_ * D_];               // attention output per batch
__device__ float  g_proj[(size_t)B_ * D_];              // fc output before LN
__device__ int    g_perm_e[TOK];
__device__ int    g_perm_u[B_];
__device__ int    g_hist_e[NT], g_base_e[NT], g_fill_e[NT];
__device__ int    g_hist_u[NT], g_base_u[NT], g_fill_u[NT];

// ---------------- prep: weights fp32 -> fp16 ----------------
__global__ void k_wconv(const float* Wq, const float* Wk, const float* Wv) {
    int m = blockIdx.y;
    const float* src = (m == 0) ? Wq : (m == 1) ? Wk : Wv;
    int i = blockIdx.x * 256 + threadIdx.x;          // < NT*WSZ = 262144
    g_W16[(size_t)m * NT * WSZ + i] = __float2half(src[i]);
}

// ---------------- tiny sort machinery ----------------
__global__ void k_zero_counters() {
    int i = threadIdx.x;
    if (i < NT) { g_hist_e[i] = 0; g_fill_e[i] = 0; g_hist_u[i] = 0; g_fill_u[i] = 0; }
}

__global__ void k_hist(const int* lab, int n, int which) {
    __shared__ int h[NT];
    if (threadIdx.x < NT) h[threadIdx.x] = 0;
    __syncthreads();
    int i = blockIdx.x * blockDim.x + threadIdx.x;
    if (i < n) atomicAdd(&h[lab[i]], 1);
    __syncthreads();
    if (threadIdx.x < NT) {
        int* hist = which ? g_hist_u : g_hist_e;
        if (h[threadIdx.x] > 0) atomicAdd(&hist[threadIdx.x], h[threadIdx.x]);
    }
}

__global__ void k_scan() {
    int s = 0;
    for (int i = 0; i < NT; i++) { g_base_e[i] = s; s += g_hist_e[i]; }
    s = 0;
    for (int i = 0; i < NT; i++) { g_base_u[i] = s; s += g_hist_u[i]; }
}

__global__ void k_assign(const int* lab, int n, int which) {
    __shared__ int h[NT], lb[NT];
    if (threadIdx.x < NT) h[threadIdx.x] = 0;
    __syncthreads();
    int i = blockIdx.x * blockDim.x + threadIdx.x;
    int e = 0, lp = 0;
    if (i < n) { e = lab[i]; lp = atomicAdd(&h[e], 1); }
    __syncthreads();
    if (threadIdx.x < NT) {
        int* fill = which ? g_fill_u : g_fill_e;
        lb[threadIdx.x] = (h[threadIdx.x] > 0) ? atomicAdd(&fill[threadIdx.x], h[threadIdx.x]) : 0;
    }
    __syncthreads();
    if (i < n) {
        const int* base = which ? g_base_u : g_base_e;
        int* perm = which ? g_perm_u : g_perm_e;
        perm[base[e] + lb[e] + lp] = i;
    }
}

// ---------------- grouped QKV projection GEMM (fp16 mma.sync) ----------------
// grid (tiles=768, e=4, mat=3); block 256 (8 warps). CTA tile: M=64, N=256, K=256 (8 chunks of 32)
__global__ void __launch_bounds__(256, 2) k_gemm(const float* q, const float* k, const float* v) {
    const int e   = blockIdx.y;
    const int mat = blockIdx.z;
    const int cnt = g_hist_e[e];
    const int row0 = blockIdx.x * 64;
    if (row0 >= cnt) return;
    const int base = g_base_e[e];
    const float* A = (mat == 0) ? q : (mat == 1) ? k : v;
    const __half* W = g_W16 + ((size_t)mat * NT + e) * WSZ;

    __shared__ __half As[2][64][34];
    __shared__ __half Bs[2][256][34];
    __shared__ int toks[64];

    const int tid = threadIdx.x;
    if (tid < 64) {
        int r = row0 + tid;
        toks[tid] = (r < cnt) ? g_perm_e[base + r] : -1;
    }
    __syncthreads();

    const int lane = tid & 31, warp = tid >> 5;
    const int wm = warp & 1, wn = warp >> 1;

    float acc[2][8][4];
#pragma unroll
    for (int a1 = 0; a1 < 2; a1++)
#pragma unroll
        for (int a2 = 0; a2 < 8; a2++)
#pragma unroll
            for (int a3 = 0; a3 < 4; a3++) acc[a1][a2][a3] = 0.f;

    auto stage = [&](int kc, int sb) {
        // A gather: 64 rows x 32 cols, fp32 -> fp16
        int arow = tid >> 2, ac0 = (tid & 3) * 8;
        int t = toks[arow];
        float4 f0 = make_float4(0.f, 0.f, 0.f, 0.f), f1 = f0;
        if (t >= 0) {
            const float4* p = (const float4*)(A + (size_t)t * D_ + kc + ac0);
            f0 = p[0]; f1 = p[1];
        }
        __half2* d = (__half2*)&As[sb][arow][ac0];
        d[0] = __floats2half2_rn(f0.x, f0.y);
        d[1] = __floats2half2_rn(f0.z, f0.w);
        d[2] = __floats2half2_rn(f1.x, f1.y);
        d[3] = __floats2half2_rn(f1.z, f1.w);
        // B: 32(k) x 256(n), store transposed Bs[n][k]
#pragma unroll
        for (int it = 0; it < 16; it++) {
            int i = it * 256 + tid;
            int kk = i >> 7;
            int n2 = (i & 127) << 1;
            __half2 wv = *(const __half2*)(W + (size_t)(kc + kk) * 256 + n2);
            Bs[sb][n2][kk]     = __low2half(wv);
            Bs[sb][n2 + 1][kk] = __high2half(wv);
        }
    };

    stage(0, 0);
    __syncthreads();

    for (int c = 0; c < 8; c++) {
        if (c < 7) stage((c + 1) * 32, (c + 1) & 1);
        int sb = c & 1;
#pragma unroll
        for (int k16 = 0; k16 < 2; k16++) {
            int kb = k16 * 16 + (lane & 3) * 2;
            int r0 = wm * 32 + (lane >> 2);
            unsigned a[2][4];
#pragma unroll
            for (int mt = 0; mt < 2; mt++) {
                a[mt][0] = *(const unsigned*)&As[sb][r0 + mt * 16    ][kb];
                a[mt][1] = *(const unsigned*)&As[sb][r0 + mt * 16 + 8][kb];
                a[mt][2] = *(const unsigned*)&As[sb][r0 + mt * 16    ][kb + 8];
                a[mt][3] = *(const unsigned*)&As[sb][r0 + mt * 16 + 8][kb + 8];
            }
#pragma unroll
            for (int nt = 0; nt < 8; nt++) {
                int n0 = wn * 64 + nt * 8 + (lane >> 2);
                unsigned b0 = *(const unsigned*)&Bs[sb][n0][kb];
                unsigned b1 = *(const unsigned*)&Bs[sb][n0][kb + 8];
#pragma unroll
                for (int mt = 0; mt < 2; mt++) {
                    asm volatile(
                        "mma.sync.aligned.m16n8k16.row.col.f32.f16.f16.f32 "
                        "{%0,%1,%2,%3},{%4,%5,%6,%7},{%8,%9},{%0,%1,%2,%3};"
                        : "+f"(acc[mt][nt][0]), "+f"(acc[mt][nt][1]),
                          "+f"(acc[mt][nt][2]), "+f"(acc[mt][nt][3])
                        : "r"(a[mt][0]), "r"(a[mt][1]), "r"(a[mt][2]), "r"(a[mt][3]),
                          "r"(b0), "r"(b1));
                }
            }
        }
        __syncthreads();
    }

    __half* Out = g_QKV + (size_t)mat * TOK * D_;
#pragma unroll
    for (int mt = 0; mt < 2; mt++) {
        int rl = wm * 32 + mt * 16 + (lane >> 2);
        int t0 = toks[rl], t1 = toks[rl + 8];
#pragma unroll
        for (int nt = 0; nt < 8; nt++) {
            int col = wn * 64 + nt * 8 + (lane & 3) * 2;
            if (t0 >= 0)
                *(__half2*)(Out + (size_t)t0 * D_ + col) = __floats2half2_rn(acc[mt][nt][0], acc[mt][nt][1]);
            if (t1 >= 0)
                *(__half2*)(Out + (size_t)t1 * D_ + col) = __floats2half2_rn(acc[mt][nt][2], acc[mt][nt][3]);
        }
    }
}

// ---------------- attention per batch ----------------
// block = one batch b: warp = head, lane = position n
__global__ void __launch_bounds__(256) k_attn(const float* rel_pri, const int* et, const int* ut,
                                              const int* mask, float* dout) {
    int b = blockIdx.x, tid = threadIdx.x, lane = tid & 31, w = tid >> 5;
    __shared__ __half Qs[32][258];
    __shared__ __half Ks[32][258];
    __shared__ float attn_s[NH][32];

    const __half* Qg = g_QKV + (size_t)0 * TOK * D_ + (size_t)b * 32 * D_;
    const __half* Kg = g_QKV + (size_t)1 * TOK * D_ + (size_t)b * 32 * D_;
    const __half* Vg = g_QKV + (size_t)2 * TOK * D_ + (size_t)b * 32 * D_;

    for (int i = tid; i < 32 * 128; i += 256) {
        int n = i >> 7, c2 = (i & 127) << 1;
        *(__half2*)&Qs[n][c2] = *(const __half2*)(Qg + n * D_ + c2);
        *(__half2*)&Ks[n][c2] = *(const __half2*)(Kg + n * D_ + c2);
    }
    __syncthreads();

    int u = ut[b];
    int n = lane, h = w;
    float acc = 0.f;
#pragma unroll
    for (int j = 0; j < 16; j++) {
        float2 qf = __half22float2(*(__half2*)&Qs[n][h * 32 + 2 * j]);
        float2 kf = __half22float2(*(__half2*)&Ks[n][h * 32 + 2 * j]);
        acc = fmaf(qf.x, kf.x, acc);
        acc = fmaf(qf.y, kf.y, acc);
    }
    float pri = rel_pri[u * NT + et[b * 32 + n]];
    float s = acc * pri * 0.17677669529663689f;   // 1/sqrt(32)
    if (mask[b * 32 + n] != 0) s = -1e10f;

    float mx = s;
#pragma unroll
    for (int o = 16; o; o >>= 1) mx = fmaxf(mx, __shfl_xor_sync(0xffffffffu, mx, o));
    float ex = expf(s - mx), sm = ex;
#pragma unroll
    for (int o = 16; o; o >>= 1) sm += __shfl_xor_sync(0xffffffffu, sm, o);
    float a = ex / sm;
    attn_s[h][n] = a;
    dout[(size_t)B_ * D_ + ((size_t)h * B_ + b) * 32 + n] = a;   // attn_flat
    __syncthreads();

    // out[h, d] = sum_n attn[h,n] * V[n][h*32+d]   (thread: h=w, d=lane)
    float o = 0.f;
#pragma unroll
    for (int nn = 0; nn < 32; nn++)
        o += attn_s[w][nn] * __half2float(Vg[nn * D_ + w * 32 + lane]);
    g_out[(size_t)b * D_ + tid] = o;
}

// ---------------- grouped FC projection (by utype) ----------------
// grid (48, NT); CTA = 32 batches x 256 cols
__global__ void __launch_bounds__(256) k_proj(const float* fc_w, const float* fc_b) {
    int u = blockIdx.y;
    int cnt = g_hist_u[u], base = g_base_u[u];
    int r0 = blockIdx.x * 32;
    if (r0 >= cnt) return;

    __shared__ float outs[32][257];
    __shared__ int bidx[32];
    int tid = threadIdx.x;
    if (tid < 32) {
        int r = r0 + tid;
        bidx[tid] = (r < cnt) ? g_perm_u[base + r] : -1;
    }
    __syncthreads();
    for (int i = tid; i < 32 * 256; i += 256) {
        int row = i >> 8, c = i & 255;
        int bb = bidx[row];
        outs[row][c] = (bb >= 0) ? g_out[(size_t)bb * D_ + c] : 0.f;
    }
    __syncthreads();

    int tj = tid & 63, tr = tid >> 6;
    int j0 = tj * 4, bb0 = tr * 8;
    float acc[8][4];
#pragma unroll
    for (int r = 0; r < 8; r++) {
        acc[r][0] = fc_b[u * D_ + j0 + 0];
        acc[r][1] = fc_b[u * D_ + j0 + 1];
        acc[r][2] = fc_b[u * D_ + j0 + 2];
        acc[r][3] = fc_b[u * D_ + j0 + 3];
    }
    const float4* fw = (const float4*)(fc_w + (size_t)u * WSZ + j0);
    for (int i = 0; i < 256; i++) {
        float4 f = fw[(size_t)i * 64];
#pragma unroll
        for (int r = 0; r < 8; r++) {
            float ov = outs[bb0 + r][i];
            acc[r][0] = fmaf(ov, f.x, acc[r][0]);
            acc[r][1] = fmaf(ov, f.y, acc[r][1]);
            acc[r][2] = fmaf(ov, f.z, acc[r][2]);
            acc[r][3] = fmaf(ov, f.w, acc[r][3]);
        }
    }
#pragma unroll
    for (int r = 0; r < 8; r++) {
        int bb = bidx[bb0 + r];
        if (bb >= 0) {
            float4 st = make_float4(acc[r][0], acc[r][1], acc[r][2], acc[r][3]);
            *(float4*)(g_proj + (size_t)bb * D_ + j0) = st;
        }
    }
}

// ---------------- LayerNorm ----------------
__global__ void __launch_bounds__(256) k_ln(const float* gamma, const float* beta, float* dout) {
    int b = blockIdx.x, tid = threadIdx.x, lane = tid & 31, w = tid >> 5;
    float p = g_proj[(size_t)b * D_ + tid];
    __shared__ float red[8];
    __shared__ float bc;

    float x = p;
#pragma unroll
    for (int o = 16; o; o >>= 1) x += __shfl_xor_sync(0xffffffffu, x, o);
    if (lane == 0) red[w] = x;
    __syncthreads();
    if (tid == 0) {
        float ss = 0.f;
        for (int i = 0; i < 8; i++) ss += red[i];
        bc = ss * (1.f / 256.f);
    }
    __syncthreads();
    float mu = bc;
    float dd = p - mu;
    __syncthreads();

    x = dd * dd;
#pragma unroll
    for (int o = 16; o; o >>= 1) x += __shfl_xor_sync(0xffffffffu, x, o);
    if (lane == 0) red[w] = x;
    __syncthreads();
    if (tid == 0) {
        float ss = 0.f;
        for (int i = 0; i < 8; i++) ss += red[i];
        bc = rsqrtf(ss * (1.f / 256.f) + 1e-5f);
    }
    __syncthreads();
    dout[(size_t)b * D_ + tid] = dd * bc * gamma[tid] + beta[tid];
}

// ---------------- launch ----------------
extern "C" void kernel_launch(void* const* d_in, const int* in_sizes, int n_in,
                              void* d_out, int out_size) {
    const float* q        = (const float*)d_in[0];
    const float* k        = (const float*)d_in[1];
    const float* v        = (const float*)d_in[2];
    const float* Wq       = (const float*)d_in[3];
    const float* Wk       = (const float*)d_in[4];
    const float* Wv       = (const float*)d_in[5];
    const float* rel_pri  = (const float*)d_in[6];
    const float* fc_w     = (const float*)d_in[7];
    const float* fc_b     = (const float*)d_in[8];
    const float* gamma    = (const float*)d_in[9];
    const float* beta     = (const float*)d_in[10];
    const int*   et       = (const int*)d_in[11];
    const int*   ut       = (const int*)d_in[12];
    const int*   mask     = (const int*)d_in[13];
    float* out = (float*)d_out;

    k_wconv<<<dim3(1024, 3), 256>>>(Wq, Wk, Wv);
    k_zero_counters<<<1, 32>>>();
    k_hist<<<512, 256>>>(et, TOK, 0);
    k_hist<<<16, 256>>>(ut, B_, 1);
    k_scan<<<1, 1>>>();
    k_assign<<<512, 256>>>(et, TOK, 0);
    k_assign<<<16, 256>>>(ut, B_, 1);
    k_gemm<<<dim3(768, NT, 3), 256>>>(q, k, v);
    k_attn<<<B_, 256>>>(rel_pri, et, ut, mask, out);
    k_proj<<<dim3(48, NT), 256>>>(fc_w, fc_b);
    k_ln<<<B_, 256>>>(gamma, beta, out);
}